// round 4
// baseline (speedup 1.0000x reference)
#include <cuda_runtime.h>
#include <cuda_bf16.h>

// GraphSAGE inference. Shapes fixed: B=4096, N0=10, N1=25, D=64, H=128.

#define B_     4096
#define N0_    10
#define N1_    25
#define D_     64
#define H1_    128
#define PAIRS  (B_ * N0_)   // 40960
#define GQ     32           // pairs per block in L1 (W1 L2-traffic amortization)
#define GB     8            // batch rows per block in L0

__device__ float g_h1[(size_t)PAIRS * H1_];            // 21 MB scratch
// Weights packed (k4, j) as ulonglong2: one LDG.128 feeds two fma.rn.f32x2.
__device__ ulonglong2 g_W1q[32 * 128];                 // K=128 -> 32 k4 steps
__device__ ulonglong2 g_W0q[48 * 128];                 // K=192 -> 48 k4 steps

// ---- packed-fp32 helpers ----
__device__ __forceinline__ unsigned long long pack2(float a, float b) {
    unsigned long long r;
    asm("mov.b64 %0, {%1, %2};" : "=l"(r) : "f"(a), "f"(b));
    return r;
}
__device__ __forceinline__ void unpack2(unsigned long long v, float& a, float& b) {
    asm("mov.b64 {%0, %1}, %2;" : "=f"(a), "=f"(b) : "l"(v));
}
__device__ __forceinline__ void ffma2(unsigned long long& d,
                                      unsigned long long a, unsigned long long b) {
    asm("fma.rn.f32x2 %0, %1, %2, %0;" : "+l"(d) : "l"(a), "l"(b));
}

__global__ void prep_w1(const float* __restrict__ W1) {   // [128,128]
    int k4 = blockIdx.x, j = threadIdx.x;
    ulonglong2 v;
    v.x = pack2(W1[(4 * k4 + 0) * 128 + j], W1[(4 * k4 + 1) * 128 + j]);
    v.y = pack2(W1[(4 * k4 + 2) * 128 + j], W1[(4 * k4 + 3) * 128 + j]);
    g_W1q[k4 * 128 + j] = v;
}
__global__ void prep_w0(const float* __restrict__ W0) {   // [192,128]
    int k4 = blockIdx.x, j = threadIdx.x;
    ulonglong2 v;
    v.x = pack2(W0[(4 * k4 + 0) * 128 + j], W0[(4 * k4 + 1) * 128 + j]);
    v.y = pack2(W0[(4 * k4 + 2) * 128 + j], W0[(4 * k4 + 3) * 128 + j]);
    g_W0q[k4 * 128 + j] = v;
}

// ---- Level-1: gather + mean(25) + fc1. 256 threads, 32 pairs per block. ----
__global__ void __launch_bounds__(256) sage_l1(
    const int*   __restrict__ neigh0,
    const int*   __restrict__ neigh1,
    const float* __restrict__ embed)
{
    __shared__ int   sn1[GQ * N1_];                  // 800 ids
    __shared__ int   sn0[GQ];
    __shared__ __align__(16) float xq[GQ][128];      // [e_n(64) | agg1(64)]

    const int t  = threadIdx.x;
    const int p0 = blockIdx.x * GQ;

    for (int i = t; i < GQ * N1_; i += 256)
        sn1[i] = neigh1[(size_t)p0 * N1_ + i];
    if (t < GQ)
        sn0[t] = neigh0[p0 + t];
    __syncthreads();

    // ---- gather: thread owns (slot, c4) and covers pairs slot, slot+16 ----
    {
        const int c4 = t & 15;
        const int pa = t >> 4;                       // pair A: 0..15
        const int pb = pa + 16;                      // pair B: 16..31
        const float4* eb = (const float4*)embed;

        float4 a = make_float4(0.f, 0.f, 0.f, 0.f);
        float4 b = make_float4(0.f, 0.f, 0.f, 0.f);
        #pragma unroll
        for (int i = 0; i < N1_; i++) {
            const float4 va = __ldg(eb + (size_t)sn1[pa * N1_ + i] * 16 + c4);
            const float4 vb = __ldg(eb + (size_t)sn1[pb * N1_ + i] * 16 + c4);
            a.x += va.x; a.y += va.y; a.z += va.z; a.w += va.w;
            b.x += vb.x; b.y += vb.y; b.z += vb.z; b.w += vb.w;
        }
        const float4 ea = __ldg(eb + (size_t)sn0[pa] * 16 + c4);
        const float4 ebv = __ldg(eb + (size_t)sn0[pb] * 16 + c4);
        *(float4*)&xq[pa][4 * c4] = ea;
        *(float4*)&xq[pb][4 * c4] = ebv;
        const float s = 1.f / (float)N1_;
        *(float4*)&xq[pa][64 + 4 * c4] = make_float4(a.x * s, a.y * s, a.z * s, a.w * s);
        *(float4*)&xq[pb][64 + 4 * c4] = make_float4(b.x * s, b.y * s, b.z * s, b.w * s);
    }
    __syncthreads();

    // ---- fc1: thread (j, ph) accumulates 16 pairs; W fetched once per block ----
    {
        const int j  = t & 127;
        const int ph = t >> 7;                       // pairs [0,16) / [16,32)
        unsigned long long acc[16];
        #pragma unroll
        for (int q = 0; q < 16; q++) acc[q] = 0ull;

        #pragma unroll 2
        for (int k4 = 0; k4 < 32; k4++) {
            const ulonglong2 w = g_W1q[k4 * 128 + j];        // LDG.128
            #pragma unroll
            for (int q = 0; q < 16; q++) {
                const ulonglong2 xv =
                    *(const ulonglong2*)&xq[ph * 16 + q][4 * k4];  // LDS.128 bcast
                ffma2(acc[q], xv.x, w.x);
                ffma2(acc[q], xv.y, w.y);
            }
        }
        #pragma unroll
        for (int q = 0; q < 16; q++) {
            float a, b; unpack2(acc[q], a, b);
            g_h1[(size_t)(p0 + ph * 16 + q) * H1_ + j] = a + b;
        }
    }
}

// ---- Level-0: mean(10) + fc0 + sigmoid. 256 threads, 8 rows/block. ----
__global__ void __launch_bounds__(256) sage_l0(
    const int*   __restrict__ inputs,
    const float* __restrict__ embed,
    const float* __restrict__ b0,
    float*       __restrict__ out)
{
    __shared__ __align__(16) float x[GB][192];       // [e_v(64) | agg0(128)]
    const int t  = threadIdx.x;
    const int j  = t & 127;
    const int h  = t >> 7;                           // row-half: rows h*4..h*4+3
    const int bb = blockIdx.x * GB;

    // ---- h1 mean: 4 rows/thread, all 40 loads issued as one batch ----
    {
        float v[4][N0_];
        #pragma unroll
        for (int q = 0; q < 4; q++) {
            const float* h1p = g_h1 + (size_t)(bb + h * 4 + q) * (N0_ * H1_) + j;
            #pragma unroll
            for (int n = 0; n < N0_; n++) v[q][n] = __ldg(h1p + n * H1_);
        }
        #pragma unroll
        for (int q = 0; q < 4; q++) {
            float s = 0.f;
            #pragma unroll
            for (int n = 0; n < N0_; n++) s += v[q][n];
            x[h * 4 + q][64 + j] = s * (1.f / (float)N0_);
        }
    }
    // e_v gathers: 512 floats spread over 256 threads
    for (int i = t; i < GB * D_; i += 256) {
        const int r = i >> 6, c = i & 63;
        x[r][c] = __ldg(embed + (size_t)__ldg(inputs + bb + r) * D_ + c);
    }
    __syncthreads();

    // ---- fc0: thread (j, h) accumulates its 4 rows ----
    unsigned long long acc[4];
    #pragma unroll
    for (int q = 0; q < 4; q++) acc[q] = 0ull;

    #pragma unroll 4
    for (int k4 = 0; k4 < 48; k4++) {
        const ulonglong2 w = g_W0q[k4 * 128 + j];            // LDG.128 (L1-shared)
        #pragma unroll
        for (int q = 0; q < 4; q++) {
            const ulonglong2 xv = *(const ulonglong2*)&x[h * 4 + q][4 * k4];
            ffma2(acc[q], xv.x, w.x);
            ffma2(acc[q], xv.y, w.y);
        }
    }
    const float bj = __ldg(b0 + j);
    #pragma unroll
    for (int q = 0; q < 4; q++) {
        float a, b; unpack2(acc[q], a, b);
        const float hv = a + b + bj;
        out[(size_t)(bb + h * 4 + q) * 128 + j] = 1.f / (1.f + __expf(-hv));
    }
}

extern "C" void kernel_launch(void* const* d_in, const int* in_sizes, int n_in,
                              void* d_out, int out_size)
{
    // Bind inputs by element count (all distinct):
    //   inputs 4096 | neigh0 40960 | neigh1 1024000 | embed 64000064
    //   W1 16384 | W0 24576 | b0 128
    const int *inputs = nullptr, *neigh0 = nullptr, *neigh1 = nullptr;
    const float *embed = nullptr, *W1 = nullptr, *W0 = nullptr, *b0 = nullptr;
    for (int i = 0; i < n_in; i++) {
        switch (in_sizes[i]) {
            case 4096:     inputs = (const int*)  d_in[i]; break;
            case 40960:    neigh0 = (const int*)  d_in[i]; break;
            case 1024000:  neigh1 = (const int*)  d_in[i]; break;
            case 64000064: embed  = (const float*)d_in[i]; break;
            case 16384:    W1     = (const float*)d_in[i]; break;
            case 24576:    W0     = (const float*)d_in[i]; break;
            case 128:      b0     = (const float*)d_in[i]; break;
        }
    }

    prep_w1<<<32, 128>>>(W1);
    prep_w0<<<48, 128>>>(W0);
    sage_l1<<<PAIRS / GQ, 256>>>(neigh0, neigh1, embed);
    sage_l0<<<B_ / GB, 256>>>(inputs, embed, b0, (float*)d_out);
}